// round 13
// baseline (speedup 1.0000x reference)
#include <cuda_runtime.h>
#include <cuda_fp16.h>
#include <stdint.h>

// ===================================================================
// Fused int8-dequant linear (sm_103 base ISA: no tcgen05).
//   out[m][n] = f32( f16( sum_k f16(x[m][k]) * (f16(wq[n][k])*f16(scale[n])) ) + f16(bias[n]) )
// Harness dtypes: x f32, weight_q i32, scale f32, bias f32, out f32.
// M=2048, N=11008, K=4096.
//
// Stage 1: merged prep kernel: W -> f16*scale, x -> f16, into scratch,
//   16KB SW128-swizzled tiles [128 rows x 64 halves].
// Stage 2: GEMM, CTA 128x256, BK=64, 4-stage cp.async.bulk ring.
//   8 compute warps (2x4, warp tile 64x64 -> 2 warps/SMSP) + 1 producer.
//   Fragment double buffering (221 regs, fits 227 budget at 288 thr).
//   Per-kt overhead amortized over 2048 tensor-cycles/SMSP.
// ===================================================================

#define NTILE_MAX 86
#define MTILE_MAX 16
#define KTILES_MAX 64

__device__ __half g_wf16[(size_t)NTILE_MAX * KTILES_MAX * 8192];
__device__ __half g_xf16[(size_t)MTILE_MAX * KTILES_MAX * 8192];

// ------------------------- PTX helpers -----------------------------
__device__ __forceinline__ uint32_t smem_u32(const void* p) {
    uint32_t a;
    asm("{ .reg .u64 t; cvta.to.shared.u64 t, %1; cvt.u32.u64 %0, t; }" : "=r"(a) : "l"(p));
    return a;
}

#define MBAR_INIT(addr, cnt) \
    asm volatile("mbarrier.init.shared.b64 [%0], %1;" :: "r"(addr), "r"(cnt) : "memory")

#define MBAR_EXPECT_TX(addr, bytes) \
    asm volatile("mbarrier.arrive.expect_tx.shared.b64 _, [%0], %1;" :: "r"(addr), "r"(bytes) : "memory")

#define MBAR_ARRIVE(addr) \
    asm volatile("mbarrier.arrive.release.cta.shared.b64 _, [%0];" :: "r"(addr) : "memory")

#define MBAR_WAIT(addr, ph) do {                                            \
    uint32_t _mb = (addr); uint32_t _p = (ph); uint32_t _done;              \
    asm volatile("{\n\t.reg .pred p;\n\t"                                   \
        "mbarrier.try_wait.parity.acquire.cta.shared::cta.b64 p, [%1], %2;\n\t" \
        "selp.b32 %0, 1, 0, p;\n\t}"                                        \
        : "=r"(_done) : "r"(_mb), "r"(_p) : "memory");                      \
    if (!_done) {                                                           \
        asm volatile("{\n\t.reg .pred P1;\n\t"                              \
            "WL_%=:\n\t"                                                    \
            "mbarrier.try_wait.parity.acquire.cta.shared::cta.b64 P1, [%0], %1, 0x989680;\n\t" \
            "@P1 bra.uni WD_%=;\n\t"                                        \
            "bra.uni WL_%=;\n\t"                                            \
            "WD_%=:\n\t}" :: "r"(_mb), "r"(_p) : "memory");                 \
    }                                                                       \
} while (0)

__device__ __forceinline__ void bulk_g2s(uint32_t dst, const void* src, uint32_t bytes, uint32_t mbar) {
    asm volatile(
        "cp.async.bulk.shared::cta.global.mbarrier::complete_tx::bytes [%0], [%1], %2, [%3];"
        :: "r"(dst), "l"(src), "r"(bytes), "r"(mbar) : "memory");
}

__device__ __forceinline__ void ldsm_x4(uint32_t r[4], uint32_t addr) {
    asm volatile("ldmatrix.sync.aligned.m8n8.x4.shared.b16 {%0,%1,%2,%3}, [%4];"
        : "=r"(r[0]), "=r"(r[1]), "=r"(r[2]), "=r"(r[3]) : "r"(addr));
}

__device__ __forceinline__ void mma16816(float d[4], const uint32_t a[4], const uint32_t b[2]) {
    asm volatile(
        "mma.sync.aligned.m16n8k16.row.col.f32.f16.f16.f32 "
        "{%0,%1,%2,%3}, {%4,%5,%6,%7}, {%8,%9}, {%0,%1,%2,%3};\n"
        : "+f"(d[0]), "+f"(d[1]), "+f"(d[2]), "+f"(d[3])
        : "r"(a[0]), "r"(a[1]), "r"(a[2]), "r"(a[3]), "r"(b[0]), "r"(b[1]));
}

__device__ __forceinline__ uint32_t sw128(uint32_t byte_off) {
    return byte_off ^ ((byte_off >> 3) & 0x70);
}

// ------------------------- merged prep kernel ----------------------
__global__ __launch_bounds__(256)
void prep_all(const int* __restrict__ wq, const float* __restrict__ scale,
              const float* __restrict__ x, int K, long wgroups, long total)
{
    long idx = (long)blockIdx.x * blockDim.x + threadIdx.x;
    if (idx >= total) return;
    const int ktiles = K >> 6;
    if (idx < wgroups) {
        int grp = (int)(idx & 1023);
        long blk = idx >> 10;
        int k_tile = (int)(blk % ktiles);
        int n_tile = (int)(blk / ktiles);
        int r  = grp >> 3;
        int c8 = grp & 7;
        int n = n_tile * 128 + r;
        int k = k_tile * 64 + c8 * 8;

        const int4* p = (const int4*)(wq + (size_t)n * K + k);
        int4 w0 = p[0], w1 = p[1];
        __half s = __float2half_rn(scale[n]);
        __half h[8];
        h[0] = __hmul(__int2half_rn(w0.x), s);
        h[1] = __hmul(__int2half_rn(w0.y), s);
        h[2] = __hmul(__int2half_rn(w0.z), s);
        h[3] = __hmul(__int2half_rn(w0.w), s);
        h[4] = __hmul(__int2half_rn(w1.x), s);
        h[5] = __hmul(__int2half_rn(w1.y), s);
        h[6] = __hmul(__int2half_rn(w1.z), s);
        h[7] = __hmul(__int2half_rn(w1.w), s);

        uint32_t off = sw128((uint32_t)(r * 128 + c8 * 16));
        *(uint4*)((char*)g_wf16 + blk * 16384 + off) = *(uint4*)h;
    } else {
        long xi = idx - wgroups;
        int grp = (int)(xi & 1023);
        long blk = xi >> 10;
        int k_tile = (int)(blk % ktiles);
        int m_tile = (int)(blk / ktiles);
        int r  = grp >> 3;
        int c8 = grp & 7;
        int m = m_tile * 128 + r;
        int k = k_tile * 64 + c8 * 8;

        const float4* p = (const float4*)(x + (size_t)m * K + k);
        float4 f0 = p[0], f1 = p[1];
        __half h[8];
        h[0] = __float2half_rn(f0.x); h[1] = __float2half_rn(f0.y);
        h[2] = __float2half_rn(f0.z); h[3] = __float2half_rn(f0.w);
        h[4] = __float2half_rn(f1.x); h[5] = __float2half_rn(f1.y);
        h[6] = __float2half_rn(f1.z); h[7] = __float2half_rn(f1.w);

        uint32_t off = sw128((uint32_t)(r * 128 + c8 * 16));
        *(uint4*)((char*)g_xf16 + blk * 16384 + off) = *(uint4*)h;
    }
}

// ------------------------- GEMM kernel -----------------------------
// CTA 128x256, BK=64. 8 compute warps (2x4, warp tile 64x64) + 1 producer.
#define NSTAGES 4
#define TILE_B 16384
#define STAGE_BYTES (3 * TILE_B)       // A(16K) + B0(16K) + B1(16K)
#define CTRL 1024
#define GEMM_SMEM (CTRL + NSTAGES * STAGE_BYTES)   // 197632 -> 1 CTA/SM
#define NTHREADS_G 288                 // 9 warps

__global__ __launch_bounds__(NTHREADS_G, 1)
void qgemm(const float* __restrict__ bias, float* __restrict__ out,
           int M, int N, int K)
{
    extern __shared__ __align__(1024) char smem[];
    const uint32_t sb = smem_u32(smem);
    const int tid  = threadIdx.x;
    const int lid  = tid & 31;
    const int warp = tid >> 5;

    const int mt_idx = blockIdx.x;         // M tile (fastest -> W L2 reuse)
    const int nt_idx = blockIdx.y;         // N tile (256 wide)
    const int ktiles = K >> 6;
    const int m0 = mt_idx * 128;
    const int n0 = nt_idx * 256;

    if (tid == 0) {
        for (int s = 0; s < NSTAGES; s++) {
            MBAR_INIT(sb + s * 8, 1);            // full
            MBAR_INIT(sb + 64 + s * 8, 8);       // empty: 8 compute warps
        }
    }
    __syncthreads();

    // ---------------- producer warp ----------------
    if (warp == 8) {
        if (lid == 0) {
            const char* Ag  = (const char*)g_xf16 + (size_t)mt_idx * ktiles * TILE_B;
            const char* B0g = (const char*)g_wf16 + (size_t)(2 * nt_idx)     * ktiles * TILE_B;
            const char* B1g = (const char*)g_wf16 + (size_t)(2 * nt_idx + 1) * ktiles * TILE_B;
            int st = 0, php = 1;
            for (int j = 0; j < ktiles; j++) {
                MBAR_WAIT(sb + 64 + st * 8, php);
                const uint32_t mbar = sb + st * 8;
                const uint32_t dst  = sb + CTRL + st * STAGE_BYTES;
                MBAR_EXPECT_TX(mbar, STAGE_BYTES);
                bulk_g2s(dst,              Ag  + (size_t)j * TILE_B, TILE_B, mbar);
                bulk_g2s(dst + TILE_B,     B0g + (size_t)j * TILE_B, TILE_B, mbar);
                bulk_g2s(dst + 2 * TILE_B, B1g + (size_t)j * TILE_B, TILE_B, mbar);
                if (++st == NSTAGES) { st = 0; php ^= 1; }
            }
        }
        return;
    }

    // -------- compute warps: 2 (M) x 4 (N), warp tile 64x64 --------
    const int wm     = (warp >> 2) * 64;   // 0,64
    const int wn     = (warp & 3) * 64;    // 0,64,128,192
    const int wn_loc = wn & 127;           // row within a 128-row B tile
    const uint32_t boff = (uint32_t)(TILE_B + (wn >> 7) * TILE_B); // B0 or B1

    const int ra       = lid & 15;
    const uint32_t swa = (uint32_t)(ra & 7) << 4;
    const uint32_t csa = (uint32_t)(lid >> 4) << 4;
    const int rb       = (lid & 7) + ((lid >> 4) << 3);
    const uint32_t swb = (uint32_t)(rb & 7) << 4;
    const uint32_t csb = (uint32_t)((lid >> 3) & 1) << 4;

    float acc[4][8][4];
#pragma unroll
    for (int i = 0; i < 4; i++)
#pragma unroll
        for (int j = 0; j < 8; j++)
#pragma unroll
            for (int c = 0; c < 4; c++) acc[i][j][c] = 0.f;

    // two fragment buffers
    uint32_t fa0[4][4], fb0[8][2];
    uint32_t fa1[4][4], fb1[8][2];

#define LOADF(FA, FB, ABASE, BBASE, KB) do {                                  \
    _Pragma("unroll")                                                         \
    for (int _mt = 0; _mt < 4; _mt++) {                                       \
        const int _r = wm + _mt * 16 + ra;                                    \
        ldsm_x4(FA[_mt], (ABASE) + (uint32_t)_r * 128 + (((KB) + csa) ^ swa));\
    }                                                                         \
    _Pragma("unroll")                                                         \
    for (int _q = 0; _q < 4; _q++) {                                          \
        const int _n = wn_loc + _q * 16 + rb;                                 \
        uint32_t _t[4];                                                       \
        ldsm_x4(_t, (BBASE) + (uint32_t)_n * 128 + (((KB) + csb) ^ swb));     \
        FB[2*_q][0] = _t[0]; FB[2*_q][1] = _t[1];                             \
        FB[2*_q+1][0] = _t[2]; FB[2*_q+1][1] = _t[3];                         \
    }                                                                         \
} while (0)

#define MMAF(FA, FB) do {                                                     \
    _Pragma("unroll")                                                         \
    for (int _mt = 0; _mt < 4; _mt++)                                         \
        _Pragma("unroll")                                                     \
        for (int _nt = 0; _nt < 8; _nt++)                                     \
            mma16816(acc[_mt][_nt], FA[_mt], FB[_nt]);                        \
} while (0)

    int st = 0, ph = 0;
    // prologue: wait stage 0, load ks0 into buf0
    MBAR_WAIT(sb + 0, 0);
    {
        const uint32_t Ab = sb + CTRL;
        const uint32_t Bb = Ab + boff;
        LOADF(fa0, fb0, Ab, Bb, 0u);
    }

    for (int kt = 0; kt < ktiles; kt++) {
        const uint32_t Abase = sb + CTRL + st * STAGE_BYTES;
        const uint32_t Bbase = Abase + boff;
        const int stn = (st + 1 == NSTAGES) ? 0 : st + 1;
        const int phn = (st + 1 == NSTAGES) ? (ph ^ 1) : ph;

        // ks0: load ks1 -> buf1, mma buf0
        LOADF(fa1, fb1, Abase, Bbase, 32u);
        MMAF(fa0, fb0);
        // ks1: load ks2 -> buf0, mma buf1
        LOADF(fa0, fb0, Abase, Bbase, 64u);
        MMAF(fa1, fb1);
        // ks2: load ks3 -> buf1; all reads of stage st now issued
        LOADF(fa1, fb1, Abase, Bbase, 96u);
        __syncwarp();
        if (lid == 0) MBAR_ARRIVE(sb + 64 + st * 8);
        MMAF(fa0, fb0);
        // ks3: peek next stage, preload its ks0 -> buf0 under last burst
        if (kt + 1 < ktiles) {
            MBAR_WAIT(sb + stn * 8, phn);
            const uint32_t Ab2 = sb + CTRL + stn * STAGE_BYTES;
            const uint32_t Bb2 = Ab2 + boff;
            LOADF(fa0, fb0, Ab2, Bb2, 0u);
        }
        MMAF(fa1, fb1);

        st = stn; ph = phn;
    }

    // ---- epilogue: h = f16(acc); h += f16(bias); out = f32(h) ----
    const int lr  = lid >> 2;
    const int lc2 = (lid & 3) * 2;
#pragma unroll
    for (int mti = 0; mti < 4; mti++) {
        const int row0 = m0 + wm + mti * 16 + lr;
        const int row1 = row0 + 8;
#pragma unroll
        for (int nti = 0; nti < 8; nti++) {
            const int col = n0 + wn + nti * 8 + lc2;
            const float2 bv = *(const float2*)&bias[col];
            const __half bh0 = __float2half_rn(bv.x);
            const __half bh1 = __float2half_rn(bv.y);

            __half h00 = __hadd(__float2half_rn(acc[mti][nti][0]), bh0);
            __half h01 = __hadd(__float2half_rn(acc[mti][nti][1]), bh1);
            __half h10 = __hadd(__float2half_rn(acc[mti][nti][2]), bh0);
            __half h11 = __hadd(__float2half_rn(acc[mti][nti][3]), bh1);

            *(float2*)&out[(size_t)row0 * N + col] =
                make_float2(__half2float(h00), __half2float(h01));
            *(float2*)&out[(size_t)row1 * N + col] =
                make_float2(__half2float(h10), __half2float(h11));
        }
    }
}

// ------------------------- launcher --------------------------------
extern "C" void kernel_launch(void* const* d_in, const int* in_sizes, int n_in,
                              void* d_out, int out_size)
{
    const float* x     = (const float*)d_in[0];
    const int*   wq    = (const int*)d_in[1];
    const float* scale = (const float*)d_in[2];
    const float* bias  = (const float*)d_in[3];
    float*       out   = (float*)d_out;

    const int N = in_sizes[3];              // 11008
    const int K = in_sizes[1] / N;          // 4096
    const int M = in_sizes[0] / K;          // 2048

    const int ktiles = K / 64;
    const long wgroups = (long)(N / 128) * ktiles * 1024;
    const long xgroups = (long)(M / 128) * ktiles * 1024;
    const long total   = wgroups + xgroups;

    static int smem_set = 0;
    if (!smem_set) {
        cudaFuncSetAttribute(qgemm, cudaFuncAttributeMaxDynamicSharedMemorySize, GEMM_SMEM);
        smem_set = 1;
    }

    prep_all<<<(unsigned)((total + 255) / 256), 256>>>(wq, scale, x, K, wgroups, total);
    dim3 grid(M / 128, N / 256);            // M fastest: W stays L2-resident
    qgemm<<<grid, NTHREADS_G, GEMM_SMEM>>>(bias, out, M, N, K);
}

// round 14
// speedup vs baseline: 2.9964x; 2.9964x over previous
#include <cuda_runtime.h>
#include <cuda_fp16.h>
#include <stdint.h>

// ===================================================================
// Fused int8-dequant linear (sm_103 base ISA: no tcgen05).
//   out[m][n] = f32( f16( sum_k f16(x[m][k]) * (f16(wq[n][k])*f16(scale[n])) ) + f16(bias[n]) )
// Harness dtypes: x f32, weight_q i32, scale f32, bias f32, out f32.
// M=2048, N=11008, K=4096.
//
// Stage 1: merged prep kernel: W -> f16*scale, x -> f16, into scratch,
//   16KB SW128-swizzled tiles [128 rows x 64 halves], k-tiles contiguous.
// Stage 2: GEMM, CTA 128x128, BK=128 (two contiguous 16KB k-tiles per
//   stage -> 32KB A + 32KB B per bulk pair), 3-stage ring.
//   8 compute warps (2x4, warp tile 64x32 -> 2 warps/SMSP, ~141 regs,
//   NO spill) + 1 producer. Fragment double buffering; 8 ks-steps/kt
//   amortize the mbar/sync overhead over 2x the MMA work.
// ===================================================================

#define NTILE_MAX 86
#define MTILE_MAX 16
#define KTILES_MAX 64

__device__ __half g_wf16[(size_t)NTILE_MAX * KTILES_MAX * 8192];
__device__ __half g_xf16[(size_t)MTILE_MAX * KTILES_MAX * 8192];

// ------------------------- PTX helpers -----------------------------
__device__ __forceinline__ uint32_t smem_u32(const void* p) {
    uint32_t a;
    asm("{ .reg .u64 t; cvta.to.shared.u64 t, %1; cvt.u32.u64 %0, t; }" : "=r"(a) : "l"(p));
    return a;
}

#define MBAR_INIT(addr, cnt) \
    asm volatile("mbarrier.init.shared.b64 [%0], %1;" :: "r"(addr), "r"(cnt) : "memory")

#define MBAR_EXPECT_TX(addr, bytes) \
    asm volatile("mbarrier.arrive.expect_tx.shared.b64 _, [%0], %1;" :: "r"(addr), "r"(bytes) : "memory")

#define MBAR_ARRIVE(addr) \
    asm volatile("mbarrier.arrive.release.cta.shared.b64 _, [%0];" :: "r"(addr) : "memory")

#define MBAR_WAIT(addr, ph) do {                                            \
    uint32_t _mb = (addr); uint32_t _p = (ph); uint32_t _done;              \
    asm volatile("{\n\t.reg .pred p;\n\t"                                   \
        "mbarrier.try_wait.parity.acquire.cta.shared::cta.b64 p, [%1], %2;\n\t" \
        "selp.b32 %0, 1, 0, p;\n\t}"                                        \
        : "=r"(_done) : "r"(_mb), "r"(_p) : "memory");                      \
    if (!_done) {                                                           \
        asm volatile("{\n\t.reg .pred P1;\n\t"                              \
            "WL_%=:\n\t"                                                    \
            "mbarrier.try_wait.parity.acquire.cta.shared::cta.b64 P1, [%0], %1, 0x989680;\n\t" \
            "@P1 bra.uni WD_%=;\n\t"                                        \
            "bra.uni WL_%=;\n\t"                                            \
            "WD_%=:\n\t}" :: "r"(_mb), "r"(_p) : "memory");                 \
    }                                                                       \
} while (0)

__device__ __forceinline__ void bulk_g2s(uint32_t dst, const void* src, uint32_t bytes, uint32_t mbar) {
    asm volatile(
        "cp.async.bulk.shared::cta.global.mbarrier::complete_tx::bytes [%0], [%1], %2, [%3];"
        :: "r"(dst), "l"(src), "r"(bytes), "r"(mbar) : "memory");
}

__device__ __forceinline__ void ldsm_x4(uint32_t r[4], uint32_t addr) {
    asm volatile("ldmatrix.sync.aligned.m8n8.x4.shared.b16 {%0,%1,%2,%3}, [%4];"
        : "=r"(r[0]), "=r"(r[1]), "=r"(r[2]), "=r"(r[3]) : "r"(addr));
}

__device__ __forceinline__ void mma16816(float d[4], const uint32_t a[4], const uint32_t b[2]) {
    asm volatile(
        "mma.sync.aligned.m16n8k16.row.col.f32.f16.f16.f32 "
        "{%0,%1,%2,%3}, {%4,%5,%6,%7}, {%8,%9}, {%0,%1,%2,%3};\n"
        : "+f"(d[0]), "+f"(d[1]), "+f"(d[2]), "+f"(d[3])
        : "r"(a[0]), "r"(a[1]), "r"(a[2]), "r"(a[3]), "r"(b[0]), "r"(b[1]));
}

__device__ __forceinline__ uint32_t sw128(uint32_t byte_off) {
    return byte_off ^ ((byte_off >> 3) & 0x70);
}

// ------------------------- merged prep kernel ----------------------
__global__ __launch_bounds__(256)
void prep_all(const int* __restrict__ wq, const float* __restrict__ scale,
              const float* __restrict__ x, int K, long wgroups, long total)
{
    long idx = (long)blockIdx.x * blockDim.x + threadIdx.x;
    if (idx >= total) return;
    const int ktiles = K >> 6;
    if (idx < wgroups) {
        int grp = (int)(idx & 1023);
        long blk = idx >> 10;
        int k_tile = (int)(blk % ktiles);
        int n_tile = (int)(blk / ktiles);
        int r  = grp >> 3;
        int c8 = grp & 7;
        int n = n_tile * 128 + r;
        int k = k_tile * 64 + c8 * 8;

        const int4* p = (const int4*)(wq + (size_t)n * K + k);
        int4 w0 = p[0], w1 = p[1];
        __half s = __float2half_rn(scale[n]);
        __half h[8];
        h[0] = __hmul(__int2half_rn(w0.x), s);
        h[1] = __hmul(__int2half_rn(w0.y), s);
        h[2] = __hmul(__int2half_rn(w0.z), s);
        h[3] = __hmul(__int2half_rn(w0.w), s);
        h[4] = __hmul(__int2half_rn(w1.x), s);
        h[5] = __hmul(__int2half_rn(w1.y), s);
        h[6] = __hmul(__int2half_rn(w1.z), s);
        h[7] = __hmul(__int2half_rn(w1.w), s);

        uint32_t off = sw128((uint32_t)(r * 128 + c8 * 16));
        *(uint4*)((char*)g_wf16 + blk * 16384 + off) = *(uint4*)h;
    } else {
        long xi = idx - wgroups;
        int grp = (int)(xi & 1023);
        long blk = xi >> 10;
        int k_tile = (int)(blk % ktiles);
        int m_tile = (int)(blk / ktiles);
        int r  = grp >> 3;
        int c8 = grp & 7;
        int m = m_tile * 128 + r;
        int k = k_tile * 64 + c8 * 8;

        const float4* p = (const float4*)(x + (size_t)m * K + k);
        float4 f0 = p[0], f1 = p[1];
        __half h[8];
        h[0] = __float2half_rn(f0.x); h[1] = __float2half_rn(f0.y);
        h[2] = __float2half_rn(f0.z); h[3] = __float2half_rn(f0.w);
        h[4] = __float2half_rn(f1.x); h[5] = __float2half_rn(f1.y);
        h[6] = __float2half_rn(f1.z); h[7] = __float2half_rn(f1.w);

        uint32_t off = sw128((uint32_t)(r * 128 + c8 * 16));
        *(uint4*)((char*)g_xf16 + blk * 16384 + off) = *(uint4*)h;
    }
}

// ------------------------- GEMM kernel -----------------------------
// CTA 128x128, BK=128. 8 compute warps (2x4, warp tile 64x32) + 1 producer.
#define NSTAGES 3
#define TILE_B 16384
#define HALF_STAGE 32768               // A or B region per stage
#define STAGE_BYTES (2 * HALF_STAGE)   // 64KB
#define CTRL 1024
#define GEMM_SMEM (CTRL + NSTAGES * STAGE_BYTES)   // 197632 -> 1 CTA/SM
#define NTHREADS_G 288                 // 9 warps

__global__ __launch_bounds__(NTHREADS_G, 1)
void qgemm(const float* __restrict__ bias, float* __restrict__ out,
           int M, int N, int K)
{
    extern __shared__ __align__(1024) char smem[];
    const uint32_t sb = smem_u32(smem);
    const int tid  = threadIdx.x;
    const int lid  = tid & 31;
    const int warp = tid >> 5;

    const int mt_idx = blockIdx.x;         // M tile (fastest -> W L2 reuse)
    const int nt_idx = blockIdx.y;         // N tile
    const int kstages = K >> 7;            // 32 (BK=128)
    const int m0 = mt_idx * 128;
    const int n0 = nt_idx * 128;

    if (tid == 0) {
        for (int s = 0; s < NSTAGES; s++) {
            MBAR_INIT(sb + s * 8, 1);            // full
            MBAR_INIT(sb + 64 + s * 8, 8);       // empty: 8 compute warps
        }
    }
    __syncthreads();

    // ---------------- producer warp ----------------
    if (warp == 8) {
        if (lid == 0) {
            const char* Ag = (const char*)g_xf16 + (size_t)mt_idx * (K >> 6) * TILE_B;
            const char* Bg = (const char*)g_wf16 + (size_t)nt_idx * (K >> 6) * TILE_B;
            int st = 0, php = 1;
            for (int j = 0; j < kstages; j++) {
                MBAR_WAIT(sb + 64 + st * 8, php);
                const uint32_t mbar = sb + st * 8;
                const uint32_t dst  = sb + CTRL + st * STAGE_BYTES;
                MBAR_EXPECT_TX(mbar, STAGE_BYTES);
                bulk_g2s(dst,              Ag + (size_t)j * HALF_STAGE, HALF_STAGE, mbar);
                bulk_g2s(dst + HALF_STAGE, Bg + (size_t)j * HALF_STAGE, HALF_STAGE, mbar);
                if (++st == NSTAGES) { st = 0; php ^= 1; }
            }
        }
        return;
    }

    // -------- compute warps: 2 (M) x 4 (N), warp tile 64x32 --------
    const int wm = (warp >> 2) * 64;     // 0,64
    const int wn = (warp & 3) * 32;      // 0,32,64,96

    const int ra       = lid & 15;
    const uint32_t swa = (uint32_t)(ra & 7) << 4;
    const uint32_t csa = (uint32_t)(lid >> 4) << 4;
    const int rb       = (lid & 7) + ((lid >> 4) << 3);
    const uint32_t swb = (uint32_t)(rb & 7) << 4;
    const uint32_t csb = (uint32_t)((lid >> 3) & 1) << 4;

    float acc[4][4][4];
#pragma unroll
    for (int i = 0; i < 4; i++)
#pragma unroll
        for (int j = 0; j < 4; j++)
#pragma unroll
            for (int c = 0; c < 4; c++) acc[i][j][c] = 0.f;

    // two fragment buffers: A 16+16, B 8+8 regs
    uint32_t fa0[4][4], fb0[4][2];
    uint32_t fa1[4][4], fb1[4][2];

#define LOADF(FA, FB, ABASE, BBASE, KB) do {                                  \
    _Pragma("unroll")                                                         \
    for (int _mt = 0; _mt < 4; _mt++) {                                       \
        const int _r = wm + _mt * 16 + ra;                                    \
        ldsm_x4(FA[_mt], (ABASE) + (uint32_t)_r * 128 + (((KB) + csa) ^ swa));\
    }                                                                         \
    _Pragma("unroll")                                                         \
    for (int _q = 0; _q < 2; _q++) {                                          \
        const int _n = wn + _q * 16 + rb;                                     \
        uint32_t _t[4];                                                       \
        ldsm_x4(_t, (BBASE) + (uint32_t)_n * 128 + (((KB) + csb) ^ swb));     \
        FB[2*_q][0] = _t[0]; FB[2*_q][1] = _t[1];                             \
        FB[2*_q+1][0] = _t[2]; FB[2*_q+1][1] = _t[3];                         \
    }                                                                         \
} while (0)

#define MMAF(FA, FB) do {                                                     \
    _Pragma("unroll")                                                         \
    for (int _mt = 0; _mt < 4; _mt++)                                         \
        _Pragma("unroll")                                                     \
        for (int _nt = 0; _nt < 4; _nt++)                                     \
            mma16816(acc[_mt][_nt], FA[_mt], FB[_nt]);                        \
} while (0)

    int st = 0, ph = 0;
    // prologue: wait stage 0, load step0 (part0, kb0) into buf0
    MBAR_WAIT(sb + 0, 0);
    LOADF(fa0, fb0, sb + CTRL, sb + CTRL + HALF_STAGE, 0u);

    for (int kt = 0; kt < kstages; kt++) {
        const uint32_t A0 = sb + CTRL + st * STAGE_BYTES;      // k-part 0
        const uint32_t A1 = A0 + TILE_B;                       // k-part 1
        const uint32_t B0 = A0 + HALF_STAGE;
        const uint32_t B1 = B0 + TILE_B;
        const int stn = (st + 1 == NSTAGES) ? 0 : st + 1;
        const int phn = (st + 1 == NSTAGES) ? (ph ^ 1) : ph;

        // 8 ks-steps (BK=128), double-buffered
        LOADF(fa1, fb1, A0, B0, 32u);  MMAF(fa0, fb0);   // s0
        LOADF(fa0, fb0, A0, B0, 64u);  MMAF(fa1, fb1);   // s1
        LOADF(fa1, fb1, A0, B0, 96u);  MMAF(fa0, fb0);   // s2
        LOADF(fa0, fb0, A1, B1, 0u);   MMAF(fa1, fb1);   // s3
        LOADF(fa1, fb1, A1, B1, 32u);  MMAF(fa0, fb0);   // s4
        LOADF(fa0, fb0, A1, B1, 64u);  MMAF(fa1, fb1);   // s5
        // s6: last reads of this stage
        LOADF(fa1, fb1, A1, B1, 96u);
        __syncwarp();
        if (lid == 0) MBAR_ARRIVE(sb + 64 + st * 8);
        MMAF(fa0, fb0);
        // s7: peek next stage, preload its step0 under the last burst
        if (kt + 1 < kstages) {
            MBAR_WAIT(sb + stn * 8, phn);
            const uint32_t An = sb + CTRL + stn * STAGE_BYTES;
            LOADF(fa0, fb0, An, An + HALF_STAGE, 0u);
        }
        MMAF(fa1, fb1);

        st = stn; ph = phn;
    }

    // ---- epilogue: h = f16(acc); h += f16(bias); out = f32(h) ----
    const int lr  = lid >> 2;
    const int lc2 = (lid & 3) * 2;
#pragma unroll
    for (int mti = 0; mti < 4; mti++) {
        const int row0 = m0 + wm + mti * 16 + lr;
        const int row1 = row0 + 8;
#pragma unroll
        for (int nti = 0; nti < 4; nti++) {
            const int col = n0 + wn + nti * 8 + lc2;
            const float2 bv = *(const float2*)&bias[col];
            const __half bh0 = __float2half_rn(bv.x);
            const __half bh1 = __float2half_rn(bv.y);

            __half h00 = __hadd(__float2half_rn(acc[mti][nti][0]), bh0);
            __half h01 = __hadd(__float2half_rn(acc[mti][nti][1]), bh1);
            __half h10 = __hadd(__float2half_rn(acc[mti][nti][2]), bh0);
            __half h11 = __hadd(__float2half_rn(acc[mti][nti][3]), bh1);

            *(float2*)&out[(size_t)row0 * N + col] =
                make_float2(__half2float(h00), __half2float(h01));
            *(float2*)&out[(size_t)row1 * N + col] =
                make_float2(__half2float(h10), __half2float(h11));
        }
    }
}

// ------------------------- launcher --------------------------------
extern "C" void kernel_launch(void* const* d_in, const int* in_sizes, int n_in,
                              void* d_out, int out_size)
{
    const float* x     = (const float*)d_in[0];
    const int*   wq    = (const int*)d_in[1];
    const float* scale = (const float*)d_in[2];
    const float* bias  = (const float*)d_in[3];
    float*       out   = (float*)d_out;

    const int N = in_sizes[3];              // 11008
    const int K = in_sizes[1] / N;          // 4096
    const int M = in_sizes[0] / K;          // 2048

    const int ktiles = K / 64;
    const long wgroups = (long)(N / 128) * ktiles * 1024;
    const long xgroups = (long)(M / 128) * ktiles * 1024;
    const long total   = wgroups + xgroups;

    static int smem_set = 0;
    if (!smem_set) {
        cudaFuncSetAttribute(qgemm, cudaFuncAttributeMaxDynamicSharedMemorySize, GEMM_SMEM);
        smem_set = 1;
    }

    prep_all<<<(unsigned)((total + 255) / 256), 256>>>(wq, scale, x, K, wgroups, total);
    dim3 grid(M / 128, N / 128);            // M fastest: W stays L2-resident
    qgemm<<<grid, NTHREADS_G, GEMM_SMEM>>>(bias, out, M, N, K);
}

// round 15
// speedup vs baseline: 3.0440x; 1.0159x over previous
#include <cuda_runtime.h>
#include <cuda_fp16.h>
#include <stdint.h>

// ===================================================================
// Fused int8-dequant linear (sm_103 base ISA: no tcgen05).
//   out[m][n] = f32( f16( sum_k f16(x[m][k]) * (f16(wq[n][k])*f16(scale[n])) ) + f16(bias[n]) )
// Harness dtypes: x f32, weight_q i32, scale f32, bias f32, out f32.
// M=2048, N=11008, K=4096.
//
// Stage 1: merged prep kernel: W -> f16*scale, x -> f16, into scratch,
//   16KB SW128-swizzled tiles [128 rows x 64 halves], k-tiles contiguous.
// Stage 2: PERSISTENT GEMM (grid = #SMs): CTA 128x128, BK=128, 3-stage
//   64KB ring streaming CONTINUOUSLY across tile boundaries. 8 compute
//   warps (2x4, 64x32, dbuf ~140 regs) + 1 producer. The s7 peek-preload
//   fetches the next tile's first fragments under the last HMMA burst, so
//   the epilogue overlaps the next tile's fill. Removes the 30%-full tail
//   wave (~28us).
// ===================================================================

#define NTILE_MAX 86
#define MTILE_MAX 16
#define KTILES_MAX 64

__device__ __half g_wf16[(size_t)NTILE_MAX * KTILES_MAX * 8192];
__device__ __half g_xf16[(size_t)MTILE_MAX * KTILES_MAX * 8192];

// ------------------------- PTX helpers -----------------------------
__device__ __forceinline__ uint32_t smem_u32(const void* p) {
    uint32_t a;
    asm("{ .reg .u64 t; cvta.to.shared.u64 t, %1; cvt.u32.u64 %0, t; }" : "=r"(a) : "l"(p));
    return a;
}

#define MBAR_INIT(addr, cnt) \
    asm volatile("mbarrier.init.shared.b64 [%0], %1;" :: "r"(addr), "r"(cnt) : "memory")

#define MBAR_EXPECT_TX(addr, bytes) \
    asm volatile("mbarrier.arrive.expect_tx.shared.b64 _, [%0], %1;" :: "r"(addr), "r"(bytes) : "memory")

#define MBAR_ARRIVE(addr) \
    asm volatile("mbarrier.arrive.release.cta.shared.b64 _, [%0];" :: "r"(addr) : "memory")

#define MBAR_WAIT(addr, ph) do {                                            \
    uint32_t _mb = (addr); uint32_t _p = (ph); uint32_t _done;              \
    asm volatile("{\n\t.reg .pred p;\n\t"                                   \
        "mbarrier.try_wait.parity.acquire.cta.shared::cta.b64 p, [%1], %2;\n\t" \
        "selp.b32 %0, 1, 0, p;\n\t}"                                        \
        : "=r"(_done) : "r"(_mb), "r"(_p) : "memory");                      \
    if (!_done) {                                                           \
        asm volatile("{\n\t.reg .pred P1;\n\t"                              \
            "WL_%=:\n\t"                                                    \
            "mbarrier.try_wait.parity.acquire.cta.shared::cta.b64 P1, [%0], %1, 0x989680;\n\t" \
            "@P1 bra.uni WD_%=;\n\t"                                        \
            "bra.uni WL_%=;\n\t"                                            \
            "WD_%=:\n\t}" :: "r"(_mb), "r"(_p) : "memory");                 \
    }                                                                       \
} while (0)

__device__ __forceinline__ void bulk_g2s(uint32_t dst, const void* src, uint32_t bytes, uint32_t mbar) {
    asm volatile(
        "cp.async.bulk.shared::cta.global.mbarrier::complete_tx::bytes [%0], [%1], %2, [%3];"
        :: "r"(dst), "l"(src), "r"(bytes), "r"(mbar) : "memory");
}

__device__ __forceinline__ void ldsm_x4(uint32_t r[4], uint32_t addr) {
    asm volatile("ldmatrix.sync.aligned.m8n8.x4.shared.b16 {%0,%1,%2,%3}, [%4];"
        : "=r"(r[0]), "=r"(r[1]), "=r"(r[2]), "=r"(r[3]) : "r"(addr));
}

__device__ __forceinline__ void mma16816(float d[4], const uint32_t a[4], const uint32_t b[2]) {
    asm volatile(
        "mma.sync.aligned.m16n8k16.row.col.f32.f16.f16.f32 "
        "{%0,%1,%2,%3}, {%4,%5,%6,%7}, {%8,%9}, {%0,%1,%2,%3};\n"
        : "+f"(d[0]), "+f"(d[1]), "+f"(d[2]), "+f"(d[3])
        : "r"(a[0]), "r"(a[1]), "r"(a[2]), "r"(a[3]), "r"(b[0]), "r"(b[1]));
}

__device__ __forceinline__ uint32_t sw128(uint32_t byte_off) {
    return byte_off ^ ((byte_off >> 3) & 0x70);
}

// ------------------------- merged prep kernel ----------------------
__global__ __launch_bounds__(256)
void prep_all(const int* __restrict__ wq, const float* __restrict__ scale,
              const float* __restrict__ x, int K, long wgroups, long total)
{
    long idx = (long)blockIdx.x * blockDim.x + threadIdx.x;
    if (idx >= total) return;
    const int ktiles = K >> 6;
    if (idx < wgroups) {
        int grp = (int)(idx & 1023);
        long blk = idx >> 10;
        int k_tile = (int)(blk % ktiles);
        int n_tile = (int)(blk / ktiles);
        int r  = grp >> 3;
        int c8 = grp & 7;
        int n = n_tile * 128 + r;
        int k = k_tile * 64 + c8 * 8;

        const int4* p = (const int4*)(wq + (size_t)n * K + k);
        int4 w0 = p[0], w1 = p[1];
        __half s = __float2half_rn(scale[n]);
        __half h[8];
        h[0] = __hmul(__int2half_rn(w0.x), s);
        h[1] = __hmul(__int2half_rn(w0.y), s);
        h[2] = __hmul(__int2half_rn(w0.z), s);
        h[3] = __hmul(__int2half_rn(w0.w), s);
        h[4] = __hmul(__int2half_rn(w1.x), s);
        h[5] = __hmul(__int2half_rn(w1.y), s);
        h[6] = __hmul(__int2half_rn(w1.z), s);
        h[7] = __hmul(__int2half_rn(w1.w), s);

        uint32_t off = sw128((uint32_t)(r * 128 + c8 * 16));
        *(uint4*)((char*)g_wf16 + blk * 16384 + off) = *(uint4*)h;
    } else {
        long xi = idx - wgroups;
        int grp = (int)(xi & 1023);
        long blk = xi >> 10;
        int k_tile = (int)(blk % ktiles);
        int m_tile = (int)(blk / ktiles);
        int r  = grp >> 3;
        int c8 = grp & 7;
        int m = m_tile * 128 + r;
        int k = k_tile * 64 + c8 * 8;

        const float4* p = (const float4*)(x + (size_t)m * K + k);
        float4 f0 = p[0], f1 = p[1];
        __half h[8];
        h[0] = __float2half_rn(f0.x); h[1] = __float2half_rn(f0.y);
        h[2] = __float2half_rn(f0.z); h[3] = __float2half_rn(f0.w);
        h[4] = __float2half_rn(f1.x); h[5] = __float2half_rn(f1.y);
        h[6] = __float2half_rn(f1.z); h[7] = __float2half_rn(f1.w);

        uint32_t off = sw128((uint32_t)(r * 128 + c8 * 16));
        *(uint4*)((char*)g_xf16 + blk * 16384 + off) = *(uint4*)h;
    }
}

// ------------------------- GEMM kernel -----------------------------
// Persistent. CTA 128x128, BK=128. 8 compute warps (2x4, 64x32) + 1 producer.
#define NSTAGES 3
#define TILE_B 16384
#define HALF_STAGE 32768               // A or B region per stage
#define STAGE_BYTES (2 * HALF_STAGE)   // 64KB
#define CTRL 1024
#define GEMM_SMEM (CTRL + NSTAGES * STAGE_BYTES)   // 197632 -> 1 CTA/SM
#define NTHREADS_G 288                 // 9 warps

__global__ __launch_bounds__(NTHREADS_G, 1)
void qgemm(const float* __restrict__ bias, float* __restrict__ out,
           int M, int N, int K)
{
    extern __shared__ __align__(1024) char smem[];
    const uint32_t sb = smem_u32(smem);
    const int tid  = threadIdx.x;
    const int lid  = tid & 31;
    const int warp = tid >> 5;
    const int cta  = blockIdx.x;
    const int ncta = gridDim.x;

    const int kstages = K >> 7;            // 32 (BK=128)
    const int mtiles  = M >> 7;            // 16
    const int ntiles  = N >> 7;            // 86
    const int otiles  = mtiles * ntiles;   // 1376

    if (tid == 0) {
        for (int s = 0; s < NSTAGES; s++) {
            MBAR_INIT(sb + s * 8, 1);            // full
            MBAR_INIT(sb + 64 + s * 8, 8);       // empty: 8 compute warps
        }
    }
    __syncthreads();

    // ---------------- producer warp: streams across tiles ----------------
    if (warp == 8) {
        if (lid == 0) {
            int st = 0, php = 1;
            for (int tt = cta; tt < otiles; tt += ncta) {
                const int mt = tt % mtiles;      // M fastest -> W L2 reuse
                const int nt = tt / mtiles;
                const char* Ag = (const char*)g_xf16 + (size_t)mt * (K >> 6) * TILE_B;
                const char* Bg = (const char*)g_wf16 + (size_t)nt * (K >> 6) * TILE_B;
                for (int j = 0; j < kstages; j++) {
                    MBAR_WAIT(sb + 64 + st * 8, php);
                    const uint32_t mbar = sb + st * 8;
                    const uint32_t dst  = sb + CTRL + st * STAGE_BYTES;
                    MBAR_EXPECT_TX(mbar, STAGE_BYTES);
                    bulk_g2s(dst,              Ag + (size_t)j * HALF_STAGE, HALF_STAGE, mbar);
                    bulk_g2s(dst + HALF_STAGE, Bg + (size_t)j * HALF_STAGE, HALF_STAGE, mbar);
                    if (++st == NSTAGES) { st = 0; php ^= 1; }
                }
            }
        }
        return;
    }

    // -------- compute warps: 2 (M) x 4 (N), warp tile 64x32 --------
    const int wm = (warp >> 2) * 64;     // 0,64
    const int wn = (warp & 3) * 32;      // 0,32,64,96

    const int ra       = lid & 15;
    const uint32_t swa = (uint32_t)(ra & 7) << 4;
    const uint32_t csa = (uint32_t)(lid >> 4) << 4;
    const int rb       = (lid & 7) + ((lid >> 4) << 3);
    const uint32_t swb = (uint32_t)(rb & 7) << 4;
    const uint32_t csb = (uint32_t)((lid >> 3) & 1) << 4;
    const int lr  = lid >> 2;
    const int lc2 = (lid & 3) * 2;

    float acc[4][4][4];
    uint32_t fa0[4][4], fb0[4][2];
    uint32_t fa1[4][4], fb1[4][2];

#define LOADF(FA, FB, ABASE, BBASE, KB) do {                                  \
    _Pragma("unroll")                                                         \
    for (int _mt = 0; _mt < 4; _mt++) {                                       \
        const int _r = wm + _mt * 16 + ra;                                    \
        ldsm_x4(FA[_mt], (ABASE) + (uint32_t)_r * 128 + (((KB) + csa) ^ swa));\
    }                                                                         \
    _Pragma("unroll")                                                         \
    for (int _q = 0; _q < 2; _q++) {                                          \
        const int _n = wn + _q * 16 + rb;                                     \
        uint32_t _t[4];                                                       \
        ldsm_x4(_t, (BBASE) + (uint32_t)_n * 128 + (((KB) + csb) ^ swb));     \
        FB[2*_q][0] = _t[0]; FB[2*_q][1] = _t[1];                             \
        FB[2*_q+1][0] = _t[2]; FB[2*_q+1][1] = _t[3];                         \
    }                                                                         \
} while (0)

#define MMAF(FA, FB) do {                                                     \
    _Pragma("unroll")                                                         \
    for (int _mt = 0; _mt < 4; _mt++)                                         \
        _Pragma("unroll")                                                     \
        for (int _nt = 0; _nt < 4; _nt++)                                     \
            mma16816(acc[_mt][_nt], FA[_mt], FB[_nt]);                        \
} while (0)

    int st = 0, ph = 0;
    bool primed = false;

    for (int tt = cta; tt < otiles; tt += ncta) {
        const int mt = tt % mtiles;
        const int nt = tt / mtiles;
        const int m0 = mt * 128;
        const int n0 = nt * 128;
        const bool last_tile = (tt + ncta >= otiles);

#pragma unroll
        for (int i = 0; i < 4; i++)
#pragma unroll
            for (int j = 0; j < 4; j++)
#pragma unroll
                for (int c = 0; c < 4; c++) acc[i][j][c] = 0.f;

        if (!primed) {
            // first tile for this CTA: wait stage 0, load step0 into buf0
            MBAR_WAIT(sb + st * 8, ph);
            LOADF(fa0, fb0, sb + CTRL + st * STAGE_BYTES,
                            sb + CTRL + st * STAGE_BYTES + HALF_STAGE, 0u);
            primed = true;
        }
        // else: fa0/fb0 already hold this tile's step0 (peek-loaded below)

        for (int kt = 0; kt < kstages; kt++) {
            const uint32_t A0 = sb + CTRL + st * STAGE_BYTES;  // k-part 0
            const uint32_t A1 = A0 + TILE_B;                   // k-part 1
            const uint32_t B0 = A0 + HALF_STAGE;
            const uint32_t B1 = B0 + TILE_B;
            const int stn = (st + 1 == NSTAGES) ? 0 : st + 1;
            const int phn = (st + 1 == NSTAGES) ? (ph ^ 1) : ph;

            LOADF(fa1, fb1, A0, B0, 32u);  MMAF(fa0, fb0);   // s0
            LOADF(fa0, fb0, A0, B0, 64u);  MMAF(fa1, fb1);   // s1
            LOADF(fa1, fb1, A0, B0, 96u);  MMAF(fa0, fb0);   // s2
            LOADF(fa0, fb0, A1, B1, 0u);   MMAF(fa1, fb1);   // s3
            LOADF(fa1, fb1, A1, B1, 32u);  MMAF(fa0, fb0);   // s4
            LOADF(fa0, fb0, A1, B1, 64u);  MMAF(fa1, fb1);   // s5
            // s6: last reads of this stage
            LOADF(fa1, fb1, A1, B1, 96u);
            __syncwarp();
            if (lid == 0) MBAR_ARRIVE(sb + 64 + st * 8);
            MMAF(fa0, fb0);
            // s7: peek next stage (this tile's next kt, or next tile's kt0)
            if (kt + 1 < kstages || !last_tile) {
                MBAR_WAIT(sb + stn * 8, phn);
                const uint32_t An = sb + CTRL + stn * STAGE_BYTES;
                LOADF(fa0, fb0, An, An + HALF_STAGE, 0u);
            }
            MMAF(fa1, fb1);

            st = stn; ph = phn;
        }

        // ---- epilogue (next tile's TMA fill streams underneath) ----
#pragma unroll
        for (int mti = 0; mti < 4; mti++) {
            const int row0 = m0 + wm + mti * 16 + lr;
            const int row1 = row0 + 8;
#pragma unroll
            for (int nti = 0; nti < 4; nti++) {
                const int col = n0 + wn + nti * 8 + lc2;
                const float2 bv = *(const float2*)&bias[col];
                const __half bh0 = __float2half_rn(bv.x);
                const __half bh1 = __float2half_rn(bv.y);

                __half h00 = __hadd(__float2half_rn(acc[mti][nti][0]), bh0);
                __half h01 = __hadd(__float2half_rn(acc[mti][nti][1]), bh1);
                __half h10 = __hadd(__float2half_rn(acc[mti][nti][2]), bh0);
                __half h11 = __hadd(__float2half_rn(acc[mti][nti][3]), bh1);

                *(float2*)&out[(size_t)row0 * N + col] =
                    make_float2(__half2float(h00), __half2float(h01));
                *(float2*)&out[(size_t)row1 * N + col] =
                    make_float2(__half2float(h10), __half2float(h11));
            }
        }
    }
}

// ------------------------- launcher --------------------------------
extern "C" void kernel_launch(void* const* d_in, const int* in_sizes, int n_in,
                              void* d_out, int out_size)
{
    const float* x     = (const float*)d_in[0];
    const int*   wq    = (const int*)d_in[1];
    const float* scale = (const float*)d_in[2];
    const float* bias  = (const float*)d_in[3];
    float*       out   = (float*)d_out;

    const int N = in_sizes[3];              // 11008
    const int K = in_sizes[1] / N;          // 4096
    const int M = in_sizes[0] / K;          // 2048

    const int ktiles = K / 64;
    const long wgroups = (long)(N / 128) * ktiles * 1024;
    const long xgroups = (long)(M / 128) * ktiles * 1024;
    const long total   = wgroups + xgroups;

    static int ncta = 0;
    if (!ncta) {
        int sms = 0;
        cudaDeviceGetAttribute(&sms, cudaDevAttrMultiProcessorCount, 0);
        ncta = sms;
        cudaFuncSetAttribute(qgemm, cudaFuncAttributeMaxDynamicSharedMemorySize, GEMM_SMEM);
    }

    prep_all<<<(unsigned)((total + 255) / 256), 256>>>(wq, scale, x, K, wgroups, total);
    qgemm<<<ncta, NTHREADS_G, GEMM_SMEM>>>(bias, out, M, N, K);
}

// round 16
// speedup vs baseline: 3.2968x; 1.0830x over previous
#include <cuda_runtime.h>
#include <cuda_fp16.h>
#include <stdint.h>

// ===================================================================
// Fused int8-dequant linear (sm_103 base ISA: no tcgen05).
//   out[m][n] = f32( f16( sum_k f16(x[m][k]) * (f16(wq[n][k])*f16(scale[n])) ) + f16(bias[n]) )
// Harness dtypes: x f32, weight_q i32, scale f32, bias f32, out f32.
// M=2048, N=11008, K=4096.
//
// Stage 1: merged prep: W -> f16*scale, x -> f16 into scratch, 16KB
//   SW128-swizzled tiles, k-tiles contiguous.
// Stage 2: PERSISTENT GEMM (grid = #SMs), CTA 128x128, BK=128, 3-stage
//   64KB ring streaming across tiles. 8 compute warps (2x4, 64x32, dbuf)
//   + 1 producer. SPLIT-K REMAINDER: the otiles%ncta leftover tiles are
//   split into 16 K-pieces each (deterministic scratch slots), killing
//   the 1-round tail imbalance (~35us of chip idle).
// Stage 3: tiny finalize kernel sums the K-pieces in fixed order and
//   applies the f16-round + f16-bias epilogue.
// ===================================================================

#define NTILE_MAX 86
#define MTILE_MAX 16
#define KTILES_MAX 64

__device__ __half g_wf16[(size_t)NTILE_MAX * KTILES_MAX * 8192];
__device__ __half g_xf16[(size_t)MTILE_MAX * KTILES_MAX * 8192];
// split-K scratch: up to 16 remainder tiles x 16 k-pieces x 128x128 f32
__device__ float  g_part[(size_t)16 * 16 * 16384];

// ------------------------- PTX helpers -----------------------------
__device__ __forceinline__ uint32_t smem_u32(const void* p) {
    uint32_t a;
    asm("{ .reg .u64 t; cvta.to.shared.u64 t, %1; cvt.u32.u64 %0, t; }" : "=r"(a) : "l"(p));
    return a;
}

#define MBAR_INIT(addr, cnt) \
    asm volatile("mbarrier.init.shared.b64 [%0], %1;" :: "r"(addr), "r"(cnt) : "memory")

#define MBAR_EXPECT_TX(addr, bytes) \
    asm volatile("mbarrier.arrive.expect_tx.shared.b64 _, [%0], %1;" :: "r"(addr), "r"(bytes) : "memory")

#define MBAR_ARRIVE(addr) \
    asm volatile("mbarrier.arrive.release.cta.shared.b64 _, [%0];" :: "r"(addr) : "memory")

#define MBAR_WAIT(addr, ph) do {                                            \
    uint32_t _mb = (addr); uint32_t _p = (ph); uint32_t _done;              \
    asm volatile("{\n\t.reg .pred p;\n\t"                                   \
        "mbarrier.try_wait.parity.acquire.cta.shared::cta.b64 p, [%1], %2;\n\t" \
        "selp.b32 %0, 1, 0, p;\n\t}"                                        \
        : "=r"(_done) : "r"(_mb), "r"(_p) : "memory");                      \
    if (!_done) {                                                           \
        asm volatile("{\n\t.reg .pred P1;\n\t"                              \
            "WL_%=:\n\t"                                                    \
            "mbarrier.try_wait.parity.acquire.cta.shared::cta.b64 P1, [%0], %1, 0x989680;\n\t" \
            "@P1 bra.uni WD_%=;\n\t"                                        \
            "bra.uni WL_%=;\n\t"                                            \
            "WD_%=:\n\t}" :: "r"(_mb), "r"(_p) : "memory");                 \
    }                                                                       \
} while (0)

__device__ __forceinline__ void bulk_g2s(uint32_t dst, const void* src, uint32_t bytes, uint32_t mbar) {
    asm volatile(
        "cp.async.bulk.shared::cta.global.mbarrier::complete_tx::bytes [%0], [%1], %2, [%3];"
        :: "r"(dst), "l"(src), "r"(bytes), "r"(mbar) : "memory");
}

__device__ __forceinline__ void ldsm_x4(uint32_t r[4], uint32_t addr) {
    asm volatile("ldmatrix.sync.aligned.m8n8.x4.shared.b16 {%0,%1,%2,%3}, [%4];"
        : "=r"(r[0]), "=r"(r[1]), "=r"(r[2]), "=r"(r[3]) : "r"(addr));
}

__device__ __forceinline__ void mma16816(float d[4], const uint32_t a[4], const uint32_t b[2]) {
    asm volatile(
        "mma.sync.aligned.m16n8k16.row.col.f32.f16.f16.f32 "
        "{%0,%1,%2,%3}, {%4,%5,%6,%7}, {%8,%9}, {%0,%1,%2,%3};\n"
        : "+f"(d[0]), "+f"(d[1]), "+f"(d[2]), "+f"(d[3])
        : "r"(a[0]), "r"(a[1]), "r"(a[2]), "r"(a[3]), "r"(b[0]), "r"(b[1]));
}

__device__ __forceinline__ uint32_t sw128(uint32_t byte_off) {
    return byte_off ^ ((byte_off >> 3) & 0x70);
}

// ------------------------- merged prep kernel ----------------------
__global__ __launch_bounds__(256)
void prep_all(const int* __restrict__ wq, const float* __restrict__ scale,
              const float* __restrict__ x, int K, long wgroups, long total)
{
    long idx = (long)blockIdx.x * blockDim.x + threadIdx.x;
    if (idx >= total) return;
    const int ktiles = K >> 6;
    if (idx < wgroups) {
        int grp = (int)(idx & 1023);
        long blk = idx >> 10;
        int k_tile = (int)(blk % ktiles);
        int n_tile = (int)(blk / ktiles);
        int r  = grp >> 3;
        int c8 = grp & 7;
        int n = n_tile * 128 + r;
        int k = k_tile * 64 + c8 * 8;

        const int4* p = (const int4*)(wq + (size_t)n * K + k);
        int4 w0 = p[0], w1 = p[1];
        __half s = __float2half_rn(scale[n]);
        __half h[8];
        h[0] = __hmul(__int2half_rn(w0.x), s);
        h[1] = __hmul(__int2half_rn(w0.y), s);
        h[2] = __hmul(__int2half_rn(w0.z), s);
        h[3] = __hmul(__int2half_rn(w0.w), s);
        h[4] = __hmul(__int2half_rn(w1.x), s);
        h[5] = __hmul(__int2half_rn(w1.y), s);
        h[6] = __hmul(__int2half_rn(w1.z), s);
        h[7] = __hmul(__int2half_rn(w1.w), s);

        uint32_t off = sw128((uint32_t)(r * 128 + c8 * 16));
        *(uint4*)((char*)g_wf16 + blk * 16384 + off) = *(uint4*)h;
    } else {
        long xi = idx - wgroups;
        int grp = (int)(xi & 1023);
        long blk = xi >> 10;
        int k_tile = (int)(blk % ktiles);
        int m_tile = (int)(blk / ktiles);
        int r  = grp >> 3;
        int c8 = grp & 7;
        int m = m_tile * 128 + r;
        int k = k_tile * 64 + c8 * 8;

        const float4* p = (const float4*)(x + (size_t)m * K + k);
        float4 f0 = p[0], f1 = p[1];
        __half h[8];
        h[0] = __float2half_rn(f0.x); h[1] = __float2half_rn(f0.y);
        h[2] = __float2half_rn(f0.z); h[3] = __float2half_rn(f0.w);
        h[4] = __float2half_rn(f1.x); h[5] = __float2half_rn(f1.y);
        h[6] = __float2half_rn(f1.z); h[7] = __float2half_rn(f1.w);

        uint32_t off = sw128((uint32_t)(r * 128 + c8 * 16));
        *(uint4*)((char*)g_xf16 + blk * 16384 + off) = *(uint4*)h;
    }
}

// ------------------------- GEMM kernel -----------------------------
// Persistent. CTA 128x128, BK=128. 8 compute warps (2x4, 64x32) + 1 producer.
#define NSTAGES 3
#define TILE_B 16384
#define HALF_STAGE 32768
#define STAGE_BYTES (2 * HALF_STAGE)   // 64KB
#define CTRL 1024
#define GEMM_SMEM (CTRL + NSTAGES * STAGE_BYTES)   // 197632 -> 1 CTA/SM
#define NTHREADS_G 288                 // 9 warps

__global__ __launch_bounds__(NTHREADS_G, 1)
void qgemm(const float* __restrict__ bias, float* __restrict__ out,
           int M, int N, int K)
{
    extern __shared__ __align__(1024) char smem[];
    const uint32_t sb = smem_u32(smem);
    const int tid  = threadIdx.x;
    const int lid  = tid & 31;
    const int warp = tid >> 5;
    const int cta  = blockIdx.x;
    const int ncta = gridDim.x;

    const int kstages = K >> 7;            // 32
    const int mtiles  = M >> 7;            // 16
    const int ntiles  = N >> 7;            // 86
    const int otiles  = mtiles * ntiles;   // 1376

    // split-K remainder config (must match host finalize decision)
    const int rem = otiles % ncta;
    const bool splitk = (rem > 0) && (rem <= 16) && ((kstages & 15) == 0)
                        && (rem * 16 <= ncta);
    const int nmain      = splitk ? otiles - rem : otiles;
    const int mainPerCta = splitk ? nmain / ncta : 0;
    const int npieces    = splitk ? rem * 16 : 0;
    const int kpp        = splitk ? (kstages >> 4) : 0;   // kstages per piece

    if (tid == 0) {
        for (int s = 0; s < NSTAGES; s++) {
            MBAR_INIT(sb + s * 8, 1);            // full
            MBAR_INIT(sb + 64 + s * 8, 8);       // empty
        }
    }
    __syncthreads();

    const int kt64 = K >> 6;   // 16KB-tile count per row block

    // ---------------- producer warp ----------------
    if (warp == 8) {
        if (lid == 0) {
            int st = 0, php = 1;
#define STREAM(TT, J0, J1) do {                                               \
    const int _mt = (TT) % mtiles;                                            \
    const int _nt = (TT) / mtiles;                                            \
    const char* _Ag = (const char*)g_xf16 + (size_t)_mt * kt64 * TILE_B;      \
    const char* _Bg = (const char*)g_wf16 + (size_t)_nt * kt64 * TILE_B;      \
    for (int _j = (J0); _j < (J1); _j++) {                                    \
        MBAR_WAIT(sb + 64 + st * 8, php);                                     \
        const uint32_t _mb = sb + st * 8;                                     \
        const uint32_t _d  = sb + CTRL + st * STAGE_BYTES;                    \
        MBAR_EXPECT_TX(_mb, STAGE_BYTES);                                     \
        bulk_g2s(_d,              _Ag + (size_t)_j * HALF_STAGE, HALF_STAGE, _mb); \
        bulk_g2s(_d + HALF_STAGE, _Bg + (size_t)_j * HALF_STAGE, HALF_STAGE, _mb); \
        if (++st == NSTAGES) { st = 0; php ^= 1; }                            \
    }                                                                         \
} while (0)
            if (splitk) {
                for (int w = 0; w < mainPerCta; w++)
                    STREAM(cta + w * ncta, 0, kstages);
                if (cta < npieces) {
                    const int tt = nmain + (cta >> 4);
                    const int j0 = (cta & 15) * kpp;
                    STREAM(tt, j0, j0 + kpp);
                }
            } else {
                for (int tt = cta; tt < otiles; tt += ncta)
                    STREAM(tt, 0, kstages);
            }
#undef STREAM
        }
        return;
    }

    // -------- compute warps: 2 (M) x 4 (N), warp tile 64x32 --------
    const int wm = (warp >> 2) * 64;
    const int wn = (warp & 3) * 32;

    const int ra       = lid & 15;
    const uint32_t swa = (uint32_t)(ra & 7) << 4;
    const uint32_t csa = (uint32_t)(lid >> 4) << 4;
    const int rb       = (lid & 7) + ((lid >> 4) << 3);
    const uint32_t swb = (uint32_t)(rb & 7) << 4;
    const uint32_t csb = (uint32_t)((lid >> 3) & 1) << 4;
    const int lr  = lid >> 2;
    const int lc2 = (lid & 3) * 2;

    float acc[4][4][4];
    uint32_t fa0[4][4], fb0[4][2];
    uint32_t fa1[4][4], fb1[4][2];

#define LOADF(FA, FB, ABASE, BBASE, KB) do {                                  \
    _Pragma("unroll")                                                         \
    for (int _mt = 0; _mt < 4; _mt++) {                                       \
        const int _r = wm + _mt * 16 + ra;                                    \
        ldsm_x4(FA[_mt], (ABASE) + (uint32_t)_r * 128 + (((KB) + csa) ^ swa));\
    }                                                                         \
    _Pragma("unroll")                                                         \
    for (int _q = 0; _q < 2; _q++) {                                          \
        const int _n = wn + _q * 16 + rb;                                     \
        uint32_t _t[4];                                                       \
        ldsm_x4(_t, (BBASE) + (uint32_t)_n * 128 + (((KB) + csb) ^ swb));     \
        FB[2*_q][0] = _t[0]; FB[2*_q][1] = _t[1];                             \
        FB[2*_q+1][0] = _t[2]; FB[2*_q+1][1] = _t[3];                         \
    }                                                                         \
} while (0)

#define MMAF(FA, FB) do {                                                     \
    _Pragma("unroll")                                                         \
    for (int _mt = 0; _mt < 4; _mt++)                                         \
        _Pragma("unroll")                                                     \
        for (int _nt = 0; _nt < 4; _nt++)                                     \
            mma16816(acc[_mt][_nt], FA[_mt], FB[_nt]);                        \
} while (0)

#define ZERO_ACC() do {                                                       \
    _Pragma("unroll")                                                         \
    for (int _i = 0; _i < 4; _i++)                                            \
        _Pragma("unroll")                                                     \
        for (int _j = 0; _j < 4; _j++)                                        \
            _Pragma("unroll")                                                 \
            for (int _c = 0; _c < 4; _c++) acc[_i][_j][_c] = 0.f;             \
} while (0)

// runs kcount BK=128 iterations; HASNEXT = more work after this item
#define RUN_KLOOP(KCOUNT, HASNEXT) do {                                       \
    for (int kt = 0; kt < (KCOUNT); kt++) {                                   \
        const uint32_t A0 = sb + CTRL + st * STAGE_BYTES;                     \
        const uint32_t A1 = A0 + TILE_B;                                      \
        const uint32_t B0 = A0 + HALF_STAGE;                                  \
        const uint32_t B1 = B0 + TILE_B;                                      \
        const int stn = (st + 1 == NSTAGES) ? 0 : st + 1;                     \
        const int phn = (st + 1 == NSTAGES) ? (ph ^ 1) : ph;                  \
        LOADF(fa1, fb1, A0, B0, 32u);  MMAF(fa0, fb0);                        \
        LOADF(fa0, fb0, A0, B0, 64u);  MMAF(fa1, fb1);                        \
        LOADF(fa1, fb1, A0, B0, 96u);  MMAF(fa0, fb0);                        \
        LOADF(fa0, fb0, A1, B1, 0u);   MMAF(fa1, fb1);                        \
        LOADF(fa1, fb1, A1, B1, 32u);  MMAF(fa0, fb0);                        \
        LOADF(fa0, fb0, A1, B1, 64u);  MMAF(fa1, fb1);                        \
        LOADF(fa1, fb1, A1, B1, 96u);                                         \
        __syncwarp();                                                         \
        if (lid == 0) MBAR_ARRIVE(sb + 64 + st * 8);                          \
        MMAF(fa0, fb0);                                                       \
        if (kt + 1 < (KCOUNT) || (HASNEXT)) {                                 \
            MBAR_WAIT(sb + stn * 8, phn);                                     \
            const uint32_t An = sb + CTRL + stn * STAGE_BYTES;                \
            LOADF(fa0, fb0, An, An + HALF_STAGE, 0u);                         \
        }                                                                     \
        MMAF(fa1, fb1);                                                       \
        st = stn; ph = phn;                                                   \
    }                                                                         \
} while (0)

    int st = 0, ph = 0;

    if (splitk) {
        const bool has_piece = (cta < npieces);
        // prime stage 0 (every CTA has at least mainPerCta>=1 work here;
        // if mainPerCta==0 and no piece, nothing to do)
        if (mainPerCta > 0 || has_piece) {
            MBAR_WAIT(sb + st * 8, ph);
            LOADF(fa0, fb0, sb + CTRL + st * STAGE_BYTES,
                            sb + CTRL + st * STAGE_BYTES + HALF_STAGE, 0u);
        }
        for (int w = 0; w < mainPerCta; w++) {
            const int tt = cta + w * ncta;
            const int m0 = (tt % mtiles) * 128;
            const int n0 = (tt / mtiles) * 128;
            ZERO_ACC();
            const bool hasnext = (w + 1 < mainPerCta) || has_piece;
            RUN_KLOOP(kstages, hasnext);
            // epilogue with bias
#pragma unroll
            for (int mti = 0; mti < 4; mti++) {
                const int row0 = m0 + wm + mti * 16 + lr;
                const int row1 = row0 + 8;
#pragma unroll
                for (int nti = 0; nti < 4; nti++) {
                    const int col = n0 + wn + nti * 8 + lc2;
                    const float2 bv = *(const float2*)&bias[col];
                    const __half bh0 = __float2half_rn(bv.x);
                    const __half bh1 = __float2half_rn(bv.y);
                    __half h00 = __hadd(__float2half_rn(acc[mti][nti][0]), bh0);
                    __half h01 = __hadd(__float2half_rn(acc[mti][nti][1]), bh1);
                    __half h10 = __hadd(__float2half_rn(acc[mti][nti][2]), bh0);
                    __half h11 = __hadd(__float2half_rn(acc[mti][nti][3]), bh1);
                    *(float2*)&out[(size_t)row0 * N + col] =
                        make_float2(__half2float(h00), __half2float(h01));
                    *(float2*)&out[(size_t)row1 * N + col] =
                        make_float2(__half2float(h10), __half2float(h11));
                }
            }
        }
        if (has_piece) {
            ZERO_ACC();
            RUN_KLOOP(kpp, false);
            // store raw f32 partial to fixed scratch slot (deterministic)
            float* dst = g_part + (size_t)cta * 16384;
#pragma unroll
            for (int mti = 0; mti < 4; mti++) {
                const int row0 = wm + mti * 16 + lr;
                const int row1 = row0 + 8;
#pragma unroll
                for (int nti = 0; nti < 4; nti++) {
                    const int col = wn + nti * 8 + lc2;
                    *(float2*)&dst[row0 * 128 + col] =
                        make_float2(acc[mti][nti][0], acc[mti][nti][1]);
                    *(float2*)&dst[row1 * 128 + col] =
                        make_float2(acc[mti][nti][2], acc[mti][nti][3]);
                }
            }
        }
    } else {
        bool primed = false;
        for (int tt = cta; tt < otiles; tt += ncta) {
            const int m0 = (tt % mtiles) * 128;
            const int n0 = (tt / mtiles) * 128;
            const bool last_tile = (tt + ncta >= otiles);
            ZERO_ACC();
            if (!primed) {
                MBAR_WAIT(sb + st * 8, ph);
                LOADF(fa0, fb0, sb + CTRL + st * STAGE_BYTES,
                                sb + CTRL + st * STAGE_BYTES + HALF_STAGE, 0u);
                primed = true;
            }
            RUN_KLOOP(kstages, !last_tile);
#pragma unroll
            for (int mti = 0; mti < 4; mti++) {
                const int row0 = m0 + wm + mti * 16 + lr;
                const int row1 = row0 + 8;
#pragma unroll
                for (int nti = 0; nti < 4; nti++) {
                    const int col = n0 + wn + nti * 8 + lc2;
                    const float2 bv = *(const float2*)&bias[col];
                    const __half bh0 = __float2half_rn(bv.x);
                    const __half bh1 = __float2half_rn(bv.y);
                    __half h00 = __hadd(__float2half_rn(acc[mti][nti][0]), bh0);
                    __half h01 = __hadd(__float2half_rn(acc[mti][nti][1]), bh1);
                    __half h10 = __hadd(__float2half_rn(acc[mti][nti][2]), bh0);
                    __half h11 = __hadd(__float2half_rn(acc[mti][nti][3]), bh1);
                    *(float2*)&out[(size_t)row0 * N + col] =
                        make_float2(__half2float(h00), __half2float(h01));
                    *(float2*)&out[(size_t)row1 * N + col] =
                        make_float2(__half2float(h10), __half2float(h11));
                }
            }
        }
    }
}

// ------------------------- finalize kernel -------------------------
// Sums the 16 K-pieces per element (fixed order), applies f16 epilogue.
__global__ __launch_bounds__(256)
void finalize(const float* __restrict__ bias, float* __restrict__ out,
              int N, int mtiles, int nmain, int rem)
{
    const int idx = blockIdx.x * 256 + threadIdx.x;
    const int total = rem * 16384;
    if (idx >= total) return;
    const int tileIdx = idx >> 14;
    const int e = idx & 16383;
    const int tt = nmain + tileIdx;
    const int mt = tt % mtiles;
    const int nt = tt / mtiles;
    const int row = e >> 7;
    const int col = e & 127;

    const float* base = g_part + (size_t)tileIdx * 16 * 16384 + e;
    float s = 0.f;
#pragma unroll
    for (int kp = 0; kp < 16; kp++) s += base[(size_t)kp * 16384];

    __half h = __hadd(__float2half_rn(s), __float2half_rn(bias[nt * 128 + col]));
    out[(size_t)(mt * 128 + row) * N + nt * 128 + col] = __half2float(h);
}

// ------------------------- launcher --------------------------------
extern "C" void kernel_launch(void* const* d_in, const int* in_sizes, int n_in,
                              void* d_out, int out_size)
{
    const float* x     = (const float*)d_in[0];
    const int*   wq    = (const int*)d_in[1];
    const float* scale = (const float*)d_in[2];
    const float* bias  = (const float*)d_in[3];
    float*       out   = (float*)d_out;

    const int N = in_sizes[3];              // 11008
    const int K = in_sizes[1] / N;          // 4096
    const int M = in_sizes[0] / K;          // 2048

    const int ktiles = K / 64;
    const long wgroups = (long)(N / 128) * ktiles * 1024;
    const long xgroups = (long)(M / 128) * ktiles * 1024;
    const long total   = wgroups + xgroups;

    static int ncta = 0;
    if (!ncta) {
        int sms = 0;
        cudaDeviceGetAttribute(&sms, cudaDevAttrMultiProcessorCount, 0);
        ncta = sms;
        cudaFuncSetAttribute(qgemm, cudaFuncAttributeMaxDynamicSharedMemorySize, GEMM_SMEM);
    }

    const int mtiles = M / 128;
    const int ntiles = N / 128;
    const int otiles = mtiles * ntiles;
    const int kstages = K / 128;
    const int rem = otiles % ncta;
    const bool splitk = (rem > 0) && (rem <= 16) && ((kstages & 15) == 0)
                        && (rem * 16 <= ncta);
    const int nmain = splitk ? otiles - rem : otiles;

    prep_all<<<(unsigned)((total + 255) / 256), 256>>>(wq, scale, x, K, wgroups, total);
    qgemm<<<ncta, NTHREADS_G, GEMM_SMEM>>>(bias, out, M, N, K);
    if (splitk) {
        const int fin_total = rem * 16384;
        finalize<<<(fin_total + 255) / 256, 256>>>(bias, out, N, mtiles, nmain, rem);
    }
}